// round 16
// baseline (speedup 1.0000x reference)
#include <cuda_runtime.h>
#include <cuda_fp16.h>
#include <math.h>

// Problem constants
#define BB 2048
#define TT 256
#define FF 64
#define HH 32
#define G3 96   // 3*H

typedef unsigned long long ull;

// Scratch for input-gate projections xg[t][b][96] in fp16 (100 MB static).
__device__ __half g_xg[(size_t)TT * BB * G3];

// ---- f32x2 packed helpers (sm_100+ PTX) -----------------------------------
__device__ __forceinline__ ull ffma2(ull a, ull b, ull c) {
    ull d;
    asm("fma.rn.f32x2 %0, %1, %2, %3;" : "=l"(d) : "l"(a), "l"(b), "l"(c));
    return d;
}
__device__ __forceinline__ ull pack2(float lo, float hi) {
    ull d;
    asm("mov.b64 %0, {%1, %2};" : "=l"(d) : "f"(lo), "f"(hi));
    return d;
}
__device__ __forceinline__ float2 unpack2f(ull p) {
    float2 r;
    asm("mov.b64 {%0, %1}, %2;" : "=f"(r.x), "=f"(r.y) : "l"(p));
    return r;
}
// Hardware tanh (MUFU.TANH; ~5e-4 max rel err)
__device__ __forceinline__ float tanh_apx(float x) {
    float y;
    asm("tanh.approx.f32 %0, %1;" : "=f"(y) : "f"(x));
    return y;
}

// ---------------------------------------------------------------------------
// Kernel 1 (unchanged from R15, measured ~164us): fp16 output.
// xg[(t*B + b)*96 + g] = sum_k x[b,t,k] * W_ih[g,k] + b_ih[g]
// ---------------------------------------------------------------------------
__global__ __launch_bounds__(192) void xg_gemm_kernel(
    const float* __restrict__ x,      // [B, T, F]
    const float* __restrict__ W_ih,   // [96, 64]
    const float* __restrict__ b_ih)   // [96]
{
    __shared__ float As[64][68];   // [k][row]  row stride 272B (16B-mult)
    __shared__ float Ws[64][100];  // [k][g]    row stride 400B (16B-mult)

    const int t  = blockIdx.y;
    const int b0 = blockIdx.x * 64;
    const int tid = threadIdx.x;        // 0..191
    const int rg = tid & 15;            // rows rg*4 .. rg*4+3
    const int cg = tid >> 4;            // cols cg*8 .. cg*8+7

    for (int idx = tid; idx < 64 * 64; idx += 192) {
        int row = idx >> 6;
        int k   = idx & 63;
        As[k][row] = x[((size_t)(b0 + row) * TT + t) * FF + k];
    }
    for (int idx = tid; idx < G3 * FF; idx += 192) {
        int g = idx >> 6;
        int k = idx & 63;
        Ws[k][g] = W_ih[idx];
    }
    __syncthreads();

    ull acc2[4][4];
#pragma unroll
    for (int v = 0; v < 4; v++) {
        ull bias = pack2(b_ih[cg * 8 + 2 * v], b_ih[cg * 8 + 2 * v + 1]);
#pragma unroll
        for (int u = 0; u < 4; u++)
            acc2[u][v] = bias;
    }

#pragma unroll
    for (int k = 0; k < 64; k++) {
        float4 a = *reinterpret_cast<const float4*>(&As[k][rg * 4]);
        ulonglong2 wa = *reinterpret_cast<const ulonglong2*>(&Ws[k][cg * 8]);
        ulonglong2 wb = *reinterpret_cast<const ulonglong2*>(&Ws[k][cg * 8 + 4]);
        ull wv[4] = {wa.x, wa.y, wb.x, wb.y};
        ull ad[4] = {pack2(a.x, a.x), pack2(a.y, a.y),
                     pack2(a.z, a.z), pack2(a.w, a.w)};
#pragma unroll
        for (int u = 0; u < 4; u++)
#pragma unroll
            for (int v = 0; v < 4; v++)
                acc2[u][v] = ffma2(ad[u], wv[v], acc2[u][v]);
    }

#pragma unroll
    for (int u = 0; u < 4; u++) {
        size_t base = ((size_t)t * BB + (b0 + rg * 4 + u)) * G3 + cg * 8;
        unsigned int q[4];
#pragma unroll
        for (int v = 0; v < 4; v++) {
            float2 f = unpack2f(acc2[u][v]);
            __half2 h2 = __floats2half2_rn(f.x, f.y);
            q[v] = *reinterpret_cast<unsigned int*>(&h2);
        }
        uint4 s = make_uint4(q[0], q[1], q[2], q[3]);
        *reinterpret_cast<uint4*>(&g_xg[base]) = s;   // 16B-aligned
    }
}

// ---------------------------------------------------------------------------
// Kernel 2: R15 shfl form + DISTANCE-2 prefetch (2x-unrolled time loop).
// Steady-state slack for the xg loads = two step times, so the per-step
// clock is no longer pinned at one full DRAM latency.
// ---------------------------------------------------------------------------
__global__ __launch_bounds__(128) void gru_recurrent_kernel(
    const float* __restrict__ W_hh,    // [96, 32]
    const float* __restrict__ b_hh,    // [96]
    const float* __restrict__ W_head,  // [32]
    const float* __restrict__ b_head,  // [1]
    float* __restrict__ out)           // [B]
{
    const int warp = (blockIdx.x * blockDim.x + threadIdx.x) >> 5;
    const int lane = threadIdx.x & 31;
    if (warp >= BB) return;
    const int b = warp;

    float wr[HH], wz[HH], wn[HH];
#pragma unroll
    for (int j = 0; j < HH; j++) {
        wr[j] = W_hh[(0 * HH + lane) * HH + j];
        wz[j] = W_hh[(1 * HH + lane) * HH + j];
        wn[j] = W_hh[(2 * HH + lane) * HH + j];
    }
    const float bhr = b_hh[lane];
    const float bhz = b_hh[HH + lane];
    const float bhn = b_hh[2 * HH + lane];

    const size_t STRIDE = (size_t)BB * G3;
    const __half* base = g_xg + (size_t)b * G3;

    float h = 0.0f;

    // Prefetch t=0 into A, t=1 into B.
    __half axr = base[lane], axz = base[HH + lane], axn = base[2 * HH + lane];
    const __half* p1 = base + STRIDE;
    __half bxr = p1[lane], bxz = p1[HH + lane], bxn = p1[2 * HH + lane];

#define GRU_STEP(XR, XZ, XN)                                                \
    {                                                                       \
        float xr = __half2float(XR);                                        \
        float xz = __half2float(XZ);                                        \
        float xn = __half2float(XN);                                        \
        float hr0 = bhr, hz0 = bhz, hn0 = bhn;                              \
        float hr1 = 0.0f, hz1 = 0.0f, hn1 = 0.0f;                           \
        _Pragma("unroll")                                                   \
        for (int j = 0; j < HH; j += 2) {                                   \
            float hj0 = __shfl_sync(0xffffffffu, h, j);                     \
            float hj1 = __shfl_sync(0xffffffffu, h, j + 1);                 \
            hr0 = fmaf(wr[j], hj0, hr0);                                    \
            hz0 = fmaf(wz[j], hj0, hz0);                                    \
            hn0 = fmaf(wn[j], hj0, hn0);                                    \
            hr1 = fmaf(wr[j + 1], hj1, hr1);                                \
            hz1 = fmaf(wz[j + 1], hj1, hz1);                                \
            hn1 = fmaf(wn[j + 1], hj1, hn1);                                \
        }                                                                   \
        float hr = hr0 + hr1;                                               \
        float hz = hz0 + hz1;                                               \
        float hn = hn0 + hn1;                                               \
        float r = fmaf(tanh_apx(0.5f * (xr + hr)), 0.5f, 0.5f);             \
        float z = fmaf(tanh_apx(0.5f * (xz + hz)), 0.5f, 0.5f);             \
        float n = tanh_apx(fmaf(r, hn, xn));                                \
        h = fmaf(z, h - n, n);                                              \
    }

    for (int t = 0; t < TT; t += 2) {
        // ---- step t: consume A; refill A with t+2 (issued before compute)
        {
            __half cxr = axr, cxz = axz, cxn = axn;
            int tp = (t + 2 < TT) ? (t + 2) : (TT - 1);
            const __half* pf = base + (size_t)tp * STRIDE;
            axr = pf[lane];
            axz = pf[HH + lane];
            axn = pf[2 * HH + lane];
            GRU_STEP(cxr, cxz, cxn);
        }
        // ---- step t+1: consume B; refill B with t+3
        {
            __half cxr = bxr, cxz = bxz, cxn = bxn;
            int tp = (t + 3 < TT) ? (t + 3) : (TT - 1);
            const __half* pf = base + (size_t)tp * STRIDE;
            bxr = pf[lane];
            bxz = pf[HH + lane];
            bxn = pf[2 * HH + lane];
            GRU_STEP(cxr, cxz, cxn);
        }
    }
#undef GRU_STEP

    // Head: y = sigmoid(h . W_head + b_head)
    float v = h * W_head[lane];
#pragma unroll
    for (int off = 16; off > 0; off >>= 1)
        v += __shfl_xor_sync(0xffffffffu, v, off);
    if (lane == 0)
        out[b] = fmaf(tanh_apx(0.5f * (v + b_head[0])), 0.5f, 0.5f);
}

// ---------------------------------------------------------------------------
extern "C" void kernel_launch(void* const* d_in, const int* in_sizes, int n_in,
                              void* d_out, int out_size)
{
    const float* x      = (const float*)d_in[0];  // [B,T,F]
    const float* W_ih   = (const float*)d_in[1];  // [96,64]
    const float* W_hh   = (const float*)d_in[2];  // [96,32]
    const float* b_ih   = (const float*)d_in[3];  // [96]
    const float* b_hh   = (const float*)d_in[4];  // [96]
    const float* W_head = (const float*)d_in[5];  // [1,32]
    const float* b_head = (const float*)d_in[6];  // [1]
    float* out = (float*)d_out;                   // [B,1] = 2048 floats

    dim3 g1(BB / 64, TT);
    xg_gemm_kernel<<<g1, 192>>>(x, W_ih, b_ih);

    gru_recurrent_kernel<<<(BB * 32) / 128, 128>>>(W_hh, b_hh, W_head, b_head, out);
}